// round 14
// baseline (speedup 1.0000x reference)
#include <cuda_runtime.h>
#include <cuda_fp16.h>
#include <math.h>

#define MAXN 100000
#define MAXE 1600000
#define MAXEP (MAXN + MAXE)
#define FD 64
#define BN_EPS 1e-5f
#define ATT_SLOPE 0.2f
#define ACT_SLOPE 0.01f

// ---------------- static device scratch ----------------
__device__ __half g_h[(size_t)MAXN * FD];    // transformed features in fp16
__device__ float  g_agg[(size_t)MAXN * FD];
__device__ float  g_ssrc[MAXN];
__device__ float  g_sdst[MAXN];
__device__ int    g_deg[MAXN];               // 1 + indegree (self-loop pre-counted)
__device__ int    g_rowstart[MAXN];          // segment start (atomic block-offset order)
__device__ int    g_cursor[MAXN];
__device__ int    g_csrsrc[MAXEP];
__device__ float  g_bnacc[2 * FD];
__device__ int    g_maxbits[4];   // [2*li]=max(0,ssrc), [2*li+1]=max(0,sdst)
__device__ int    g_ecur;                    // global segment-space cursor

#define SCAN_BS 512

// ---------------- CSR build ----------------
__global__ void zero_kernel(int n) {
    int i = blockIdx.x * blockDim.x + threadIdx.x;
    if (i < n) g_deg[i] = 1;              // self-loop pre-counted
    if (i < 2 * FD) g_bnacc[i] = 0.0f;
    if (i < 4) g_maxbits[i] = 0;
    if (i == 0) g_ecur = 0;
}

__global__ void count_kernel(const int* __restrict__ ei, int e) {
    int i = (blockIdx.x * blockDim.x + threadIdx.x) * 4;
    if (i + 3 < e) {
        int4 d = *(const int4*)&ei[e + i];
        atomicAdd(&g_deg[d.x], 1);
        atomicAdd(&g_deg[d.y], 1);
        atomicAdd(&g_deg[d.z], 1);
        atomicAdd(&g_deg[d.w], 1);
    } else {
        for (int j = i; j < e; j++) atomicAdd(&g_deg[ei[e + j]], 1);
    }
}

// block-local scan + one atomicAdd for the block's offset; writes rowstart/cursor/self-loop
__global__ void scanA_kernel(int n) {
    __shared__ int sh[SCAN_BS];
    __shared__ int boff_s;
    int tid = threadIdx.x;
    int idx = blockIdx.x * SCAN_BS + tid;
    int v = (idx < n) ? g_deg[idx] : 0;
    sh[tid] = v;
    __syncthreads();
    for (int off = 1; off < SCAN_BS; off <<= 1) {
        int t = (tid >= off) ? sh[tid - off] : 0;
        __syncthreads();
        sh[tid] += t;
        __syncthreads();
    }
    if (tid == SCAN_BS - 1) boff_s = atomicAdd(&g_ecur, sh[tid]);
    __syncthreads();
    if (idx < n) {
        int r = boff_s + sh[tid] - v;     // block-local exclusive + block offset
        g_rowstart[idx] = r;
        g_csrsrc[r] = idx;                // self-loop occupies slot 0 of the segment
        g_cursor[idx] = r + 1;
    }
}

__global__ void fill_kernel(const int* __restrict__ ei, int e) {
    int i = (blockIdx.x * blockDim.x + threadIdx.x) * 4;
    if (i + 3 < e) {
        int4 s = *(const int4*)&ei[i];
        int4 d = *(const int4*)&ei[e + i];
        g_csrsrc[atomicAdd(&g_cursor[d.x], 1)] = s.x;
        g_csrsrc[atomicAdd(&g_cursor[d.y], 1)] = s.y;
        g_csrsrc[atomicAdd(&g_cursor[d.z], 1)] = s.z;
        g_csrsrc[atomicAdd(&g_cursor[d.w], 1)] = s.w;
    } else {
        for (int j = i; j < e; j++)
            g_csrsrc[atomicAdd(&g_cursor[ei[e + j]], 1)] = ei[j];
    }
}

// ---------------- GEMM: H = X @ W (fp32 math, fp16 store), fused scores + global max ----------------
__global__ void gemm_kernel(const float* __restrict__ X, const float* __restrict__ W,
                            const float* __restrict__ a_src, const float* __restrict__ a_dst,
                            __half* __restrict__ H, float* __restrict__ ssrc, float* __restrict__ sdst,
                            int n, int apply_bn,
                            const float* __restrict__ bng, const float* __restrict__ bnb, int li) {
    __shared__ float Ws[FD * FD];
    __shared__ float xs[64][FD + 4];
    __shared__ float as[FD], ad[FD], sc[FD], shf[FD];
    __shared__ float wmaxS[8], wmaxD[8];

    int tid = threadIdx.x;
    for (int i = tid; i < FD * FD / 4; i += 256)
        ((float4*)Ws)[i] = ((const float4*)W)[i];
    if (tid < FD) {
        as[tid] = a_src[tid];
        ad[tid] = a_dst[tid];
        if (apply_bn) {
            float invn = 1.0f / (float)n;
            float mean = g_bnacc[tid] * invn;
            float var  = g_bnacc[FD + tid] * invn - mean * mean;
            float istd = rsqrtf(var + BN_EPS);
            float s = istd * bng[tid];
            sc[tid]  = s;
            shf[tid] = bnb[tid] - mean * s;
        }
    }
    __syncthreads();

    int row0 = blockIdx.x * 64;
    for (int i = tid; i < 64 * FD / 4; i += 256) {
        int lr = i >> 4;
        int c4 = (i & 15) * 4;
        int gr = row0 + lr;
        float4 v = make_float4(0.f, 0.f, 0.f, 0.f);
        if (gr < n) v = ((const float4*)X)[(size_t)gr * 16 + (i & 15)];
        if (apply_bn) {
            v.x = v.x * sc[c4]     + shf[c4];
            v.y = v.y * sc[c4 + 1] + shf[c4 + 1];
            v.z = v.z * sc[c4 + 2] + shf[c4 + 2];
            v.w = v.w * sc[c4 + 3] + shf[c4 + 3];
            v.x = (v.x > 0.f) ? v.x : ACT_SLOPE * v.x;
            v.y = (v.y > 0.f) ? v.y : ACT_SLOPE * v.y;
            v.z = (v.z > 0.f) ? v.z : ACT_SLOPE * v.z;
            v.w = (v.w > 0.f) ? v.w : ACT_SLOPE * v.w;
        }
        *(float4*)&xs[lr][c4] = v;
    }
    __syncthreads();

    int ty = tid >> 4, tx = tid & 15;
    int r0 = ty * 4, c0 = tx * 4;
    float acc[4][4];
#pragma unroll
    for (int i = 0; i < 4; i++)
#pragma unroll
        for (int j = 0; j < 4; j++) acc[i][j] = 0.f;

#pragma unroll 16
    for (int k = 0; k < FD; k++) {
        float4 wv = *(const float4*)&Ws[k * FD + c0];
        float x0 = xs[r0][k], x1 = xs[r0 + 1][k], x2 = xs[r0 + 2][k], x3 = xs[r0 + 3][k];
        acc[0][0] += x0 * wv.x; acc[0][1] += x0 * wv.y; acc[0][2] += x0 * wv.z; acc[0][3] += x0 * wv.w;
        acc[1][0] += x1 * wv.x; acc[1][1] += x1 * wv.y; acc[1][2] += x1 * wv.z; acc[1][3] += x1 * wv.w;
        acc[2][0] += x2 * wv.x; acc[2][1] += x2 * wv.y; acc[2][2] += x2 * wv.z; acc[2][3] += x2 * wv.w;
        acc[3][0] += x3 * wv.x; acc[3][1] += x3 * wv.y; acc[3][2] += x3 * wv.z; acc[3][3] += x3 * wv.w;
    }

    float lmS = 0.f, lmD = 0.f;
#pragma unroll
    for (int i = 0; i < 4; i++) {
        int row = row0 + r0 + i;
        if (row < n) {
            __half2 h01 = __floats2half2_rn(acc[i][0], acc[i][1]);
            __half2 h23 = __floats2half2_rn(acc[i][2], acc[i][3]);
            uint2 pk;
            pk.x = *(unsigned*)&h01;
            pk.y = *(unsigned*)&h23;
            ((uint2*)H)[(size_t)row * 16 + tx] = pk;
        }
        float ps = acc[i][0] * as[c0] + acc[i][1] * as[c0 + 1] + acc[i][2] * as[c0 + 2] + acc[i][3] * as[c0 + 3];
        float pd = acc[i][0] * ad[c0] + acc[i][1] * ad[c0 + 1] + acc[i][2] * ad[c0 + 2] + acc[i][3] * ad[c0 + 3];
#pragma unroll
        for (int o = 8; o; o >>= 1) {
            ps += __shfl_down_sync(0xffffffffu, ps, o, 16);
            pd += __shfl_down_sync(0xffffffffu, pd, o, 16);
        }
        if (tx == 0 && row < n) {
            ssrc[row] = ps;
            sdst[row] = pd;
            lmS = fmaxf(lmS, ps);
            lmD = fmaxf(lmD, pd);
        }
    }
#pragma unroll
    for (int o = 16; o; o >>= 1) {
        lmS = fmaxf(lmS, __shfl_xor_sync(0xffffffffu, lmS, o));
        lmD = fmaxf(lmD, __shfl_xor_sync(0xffffffffu, lmD, o));
    }
    int wid = tid >> 5;
    if ((tid & 31) == 0) { wmaxS[wid] = lmS; wmaxD[wid] = lmD; }
    __syncthreads();
    if (tid == 0) {
        float mS = 0.f, mD = 0.f;
#pragma unroll
        for (int w = 0; w < 8; w++) { mS = fmaxf(mS, wmaxS[w]); mD = fmaxf(mD, wmaxD[w]); }
        atomicMax(&g_maxbits[2 * li],     __float_as_int(mS));
        atomicMax(&g_maxbits[2 * li + 1], __float_as_int(mD));
    }
}

// ---------------- Aggregation: warp per dst node, smem (s,w) staging, unroll-4 gather ----------------
#define CHUNK 64
#define AGG_BS 512
__global__ void __launch_bounds__(AGG_BS)
agg_kernel(const __half* __restrict__ H,
           const float* __restrict__ ssrc, const float* __restrict__ sdst,
           const float* __restrict__ bias,
           const float* __restrict__ x0,
           float* __restrict__ out, int n, int residual, int li) {
    __shared__ int2 swbuf[AGG_BS / 32][CHUNK];
    int wwarp = threadIdx.x >> 5;
    int warp = (blockIdx.x * blockDim.x + threadIdx.x) >> 5;
    int lane = threadIdx.x & 31;
    if (warp >= n) return;
    float M = __int_as_float(g_maxbits[2 * li]) + __int_as_float(g_maxbits[2 * li + 1]);
    int start = g_rowstart[warp];
    int end   = start + g_deg[warp];
    float sd = sdst[warp];
    int q = lane >> 3, sub = lane & 7;

    float z = 0.0f;
    float acc[8];
#pragma unroll
    for (int i = 0; i < 8; i++) acc[i] = 0.f;
    const uint4* H8 = (const uint4*)H;

    for (int cbase = start; cbase < end; cbase += CHUNK) {
        int cnt = min(CHUNK, end - cbase);
        // ---- phase W: compute (s, w) coalesced, stage to smem ----
        for (int t = cbase + lane; t < cbase + cnt; t += 32) {
            int s = g_csrsrc[t];
            float lg = ssrc[s] + sd;
            lg = (lg > 0.0f) ? lg : ATT_SLOPE * lg;
            float w = __expf(lg - M);
            z += w;
            swbuf[wwarp][t - cbase] = make_int2(s, __float_as_int(w));
        }
        __syncwarp();
        // ---- phase G: quarter-warp per edge, broadcast LDS, 4 LDGs in flight ----
#pragma unroll 4
        for (int j = 0; j < cnt; j += 4) {
            int idx = j + q;
            int2 sw = (idx < cnt) ? swbuf[wwarp][idx] : make_int2(0, 0);
            float ej = __int_as_float(sw.y);          // 0.0f when idx >= cnt
            uint4 hv = __ldg(&H8[(size_t)sw.x * 8 + sub]);
            float2 f0 = __half22float2(*(__half2*)&hv.x);
            float2 f1 = __half22float2(*(__half2*)&hv.y);
            float2 f2 = __half22float2(*(__half2*)&hv.z);
            float2 f3 = __half22float2(*(__half2*)&hv.w);
            acc[0] += ej * f0.x; acc[1] += ej * f0.y;
            acc[2] += ej * f1.x; acc[3] += ej * f1.y;
            acc[4] += ej * f2.x; acc[5] += ej * f2.y;
            acc[6] += ej * f3.x; acc[7] += ej * f3.y;
        }
        __syncwarp();
    }
#pragma unroll
    for (int i = 0; i < 8; i++) {
        acc[i] += __shfl_xor_sync(0xffffffffu, acc[i], 8);
        acc[i] += __shfl_xor_sync(0xffffffffu, acc[i], 16);
    }
#pragma unroll
    for (int o = 16; o; o >>= 1) z += __shfl_xor_sync(0xffffffffu, z, o);

    if (q == 0) {
        float inv = 1.0f / z;
        float4 b0 = ((const float4*)bias)[sub * 2];
        float4 b1 = ((const float4*)bias)[sub * 2 + 1];
        float4 r0, r1;
        r0.x = acc[0] * inv + b0.x;
        r0.y = acc[1] * inv + b0.y;
        r0.z = acc[2] * inv + b0.z;
        r0.w = acc[3] * inv + b0.w;
        r1.x = acc[4] * inv + b1.x;
        r1.y = acc[5] * inv + b1.y;
        r1.z = acc[6] * inv + b1.z;
        r1.w = acc[7] * inv + b1.w;
        if (residual) {
            float4 xv0 = ((const float4*)x0)[(size_t)warp * 16 + sub * 2];
            float4 xv1 = ((const float4*)x0)[(size_t)warp * 16 + sub * 2 + 1];
            r0.x = 0.5f * (xv0.x + r0.x); r0.y = 0.5f * (xv0.y + r0.y);
            r0.z = 0.5f * (xv0.z + r0.z); r0.w = 0.5f * (xv0.w + r0.w);
            r1.x = 0.5f * (xv1.x + r1.x); r1.y = 0.5f * (xv1.y + r1.y);
            r1.z = 0.5f * (xv1.z + r1.z); r1.w = 0.5f * (xv1.w + r1.w);
        }
        ((float4*)out)[(size_t)warp * 16 + sub * 2]     = r0;
        ((float4*)out)[(size_t)warp * 16 + sub * 2 + 1] = r1;
    }
}

// ---------------- BN statistics ----------------
__global__ void bnstats_kernel(const float* __restrict__ A, int n) {
    __shared__ float s1[256], s2[256];
    int tid = threadIdx.x;
    int c = tid & 63;
    int q = tid >> 6;
    float sum = 0.f, sq = 0.f;
    int row0 = blockIdx.x * 64;
    for (int rr = q; rr < 64; rr += 4) {
        int row = row0 + rr;
        if (row < n) {
            float v = A[(size_t)row * FD + c];
            sum += v;
            sq  += v * v;
        }
    }
    s1[tid] = sum; s2[tid] = sq;
    __syncthreads();
    if (q == 0) {
        sum = s1[c] + s1[64 + c] + s1[128 + c] + s1[192 + c];
        sq  = s2[c] + s2[64 + c] + s2[128 + c] + s2[192 + c];
        atomicAdd(&g_bnacc[c], sum);
        atomicAdd(&g_bnacc[FD + c], sq);
    }
}

// ---------------- launch (single stream; agg1 is launch index 5 for ncu -s 5) ----------------
extern "C" void kernel_launch(void* const* d_in, const int* in_sizes, int n_in,
                              void* d_out, int out_size) {
    const float* x        = (const float*)d_in[0];
    const float* W1       = (const float*)d_in[1];
    const float* att_src1 = (const float*)d_in[2];
    const float* att_dst1 = (const float*)d_in[3];
    const float* bias1    = (const float*)d_in[4];
    const float* bn_gamma = (const float*)d_in[5];
    const float* bn_beta  = (const float*)d_in[6];
    const float* W2       = (const float*)d_in[7];
    const float* att_src2 = (const float*)d_in[8];
    const float* att_dst2 = (const float*)d_in[9];
    const float* bias2    = (const float*)d_in[10];
    const int*   ei       = (const int*)d_in[11];

    int n = in_sizes[0] / FD;
    int e = in_sizes[11] / 2;

    float* out = (float*)d_out;

    __half* d_h   = nullptr;
    float* d_agg  = nullptr;
    float* d_ssrc = nullptr;
    float* d_sdst = nullptr;
    cudaGetSymbolAddress((void**)&d_h, g_h);
    cudaGetSymbolAddress((void**)&d_agg, g_agg);
    cudaGetSymbolAddress((void**)&d_ssrc, g_ssrc);
    cudaGetSymbolAddress((void**)&d_sdst, g_sdst);

    int nb = (n + SCAN_BS - 1) / SCAN_BS;
    int gemm_grid = (n + 63) / 64;
    int agg_grid  = (n + (AGG_BS / 32) - 1) / (AGG_BS / 32);
    int e4 = (e + 3) / 4;

    // [0] prologue
    zero_kernel<<<(n + 255) / 256, 256>>>(n);
    // [1..3] CSR build (2-launch scan via atomic block offsets)
    count_kernel<<<(e4 + 255) / 256, 256>>>(ei, e);
    scanA_kernel<<<nb, SCAN_BS>>>(n);
    fill_kernel<<<(e4 + 255) / 256, 256>>>(ei, e);
    // [4] Layer-1 GEMM
    gemm_kernel<<<gemm_grid, 256>>>(x, W1, att_src1, att_dst1,
                                    d_h, d_ssrc, d_sdst, n, 0, nullptr, nullptr, 0);
    // [5] Layer-1 aggregation  <-- ncu -s 5 capture target
    agg_kernel<<<agg_grid, AGG_BS>>>(d_h, d_ssrc, d_sdst, bias1, nullptr, d_agg, n, 0, 0);
    // [6] BN stats
    bnstats_kernel<<<(n + 63) / 64, 256>>>(d_agg, n);
    // [7..8] Layer 2
    gemm_kernel<<<gemm_grid, 256>>>(d_agg, W2, att_src2, att_dst2,
                                    d_h, d_ssrc, d_sdst, n, 1, bn_gamma, bn_beta, 1);
    agg_kernel<<<agg_grid, AGG_BS>>>(d_h, d_ssrc, d_sdst, bias2, x, out, n, 1, 1);
}

// round 15
// speedup vs baseline: 1.0942x; 1.0942x over previous
#include <cuda_runtime.h>
#include <cuda_fp16.h>
#include <math.h>

#define MAXN 100000
#define MAXE 1600000
#define MAXEP (MAXN + MAXE)
#define FD 64
#define BN_EPS 1e-5f
#define ATT_SLOPE 0.2f
#define ACT_SLOPE 0.01f

// ---------------- static device scratch ----------------
__device__ __half g_h[(size_t)MAXN * FD];    // transformed features in fp16
__device__ float  g_agg[(size_t)MAXN * FD];
__device__ float  g_ssrc[MAXN];
__device__ float  g_sdst[MAXN];
__device__ int    g_deg[MAXN];               // 1 + indegree (self-loop pre-counted)
__device__ int    g_rowstart[MAXN];          // segment start (atomic block-offset order)
__device__ int    g_cursor[MAXN];
__device__ int    g_csrsrc[MAXEP];
__device__ float  g_bnacc[2 * FD];
__device__ int    g_maxbits[4];   // [2*li]=max(0,ssrc), [2*li+1]=max(0,sdst)
__device__ int    g_ecur;                    // global segment-space cursor

#define SCAN_BS 512

// ---------------- CSR build ----------------
__global__ void zero_kernel(int n) {
    int i = blockIdx.x * blockDim.x + threadIdx.x;
    if (i < n) g_deg[i] = 1;              // self-loop pre-counted
    if (i < 2 * FD) g_bnacc[i] = 0.0f;
    if (i < 4) g_maxbits[i] = 0;
    if (i == 0) g_ecur = 0;
}

__global__ void count_kernel(const int* __restrict__ ei, int e) {
    int i = (blockIdx.x * blockDim.x + threadIdx.x) * 4;
    if (i + 3 < e) {
        int4 d = *(const int4*)&ei[e + i];
        atomicAdd(&g_deg[d.x], 1);
        atomicAdd(&g_deg[d.y], 1);
        atomicAdd(&g_deg[d.z], 1);
        atomicAdd(&g_deg[d.w], 1);
    } else {
        for (int j = i; j < e; j++) atomicAdd(&g_deg[ei[e + j]], 1);
    }
}

// block-local scan + one atomicAdd for the block's offset; writes rowstart/cursor/self-loop
__global__ void scanA_kernel(int n) {
    __shared__ int sh[SCAN_BS];
    __shared__ int boff_s;
    int tid = threadIdx.x;
    int idx = blockIdx.x * SCAN_BS + tid;
    int v = (idx < n) ? g_deg[idx] : 0;
    sh[tid] = v;
    __syncthreads();
    for (int off = 1; off < SCAN_BS; off <<= 1) {
        int t = (tid >= off) ? sh[tid - off] : 0;
        __syncthreads();
        sh[tid] += t;
        __syncthreads();
    }
    if (tid == SCAN_BS - 1) boff_s = atomicAdd(&g_ecur, sh[tid]);
    __syncthreads();
    if (idx < n) {
        int r = boff_s + sh[tid] - v;     // block-local exclusive + block offset
        g_rowstart[idx] = r;
        g_csrsrc[r] = idx;                // self-loop occupies slot 0 of the segment
        g_cursor[idx] = r + 1;
    }
}

__global__ void fill_kernel(const int* __restrict__ ei, int e) {
    int i = (blockIdx.x * blockDim.x + threadIdx.x) * 4;
    if (i + 3 < e) {
        int4 s = *(const int4*)&ei[i];
        int4 d = *(const int4*)&ei[e + i];
        g_csrsrc[atomicAdd(&g_cursor[d.x], 1)] = s.x;
        g_csrsrc[atomicAdd(&g_cursor[d.y], 1)] = s.y;
        g_csrsrc[atomicAdd(&g_cursor[d.z], 1)] = s.z;
        g_csrsrc[atomicAdd(&g_cursor[d.w], 1)] = s.w;
    } else {
        for (int j = i; j < e; j++)
            g_csrsrc[atomicAdd(&g_cursor[ei[e + j]], 1)] = ei[j];
    }
}

// ---------------- GEMM: H = X @ W (fp32 math, fp16 store), fused scores + global max ----------------
__global__ void gemm_kernel(const float* __restrict__ X, const float* __restrict__ W,
                            const float* __restrict__ a_src, const float* __restrict__ a_dst,
                            __half* __restrict__ H, float* __restrict__ ssrc, float* __restrict__ sdst,
                            int n, int apply_bn,
                            const float* __restrict__ bng, const float* __restrict__ bnb, int li) {
    __shared__ float Ws[FD * FD];
    __shared__ float xs[64][FD + 4];
    __shared__ float as[FD], ad[FD], sc[FD], shf[FD];
    __shared__ float wmaxS[8], wmaxD[8];

    int tid = threadIdx.x;
    for (int i = tid; i < FD * FD / 4; i += 256)
        ((float4*)Ws)[i] = ((const float4*)W)[i];
    if (tid < FD) {
        as[tid] = a_src[tid];
        ad[tid] = a_dst[tid];
        if (apply_bn) {
            float invn = 1.0f / (float)n;
            float mean = g_bnacc[tid] * invn;
            float var  = g_bnacc[FD + tid] * invn - mean * mean;
            float istd = rsqrtf(var + BN_EPS);
            float s = istd * bng[tid];
            sc[tid]  = s;
            shf[tid] = bnb[tid] - mean * s;
        }
    }
    __syncthreads();

    int row0 = blockIdx.x * 64;
    for (int i = tid; i < 64 * FD / 4; i += 256) {
        int lr = i >> 4;
        int c4 = (i & 15) * 4;
        int gr = row0 + lr;
        float4 v = make_float4(0.f, 0.f, 0.f, 0.f);
        if (gr < n) v = ((const float4*)X)[(size_t)gr * 16 + (i & 15)];
        if (apply_bn) {
            v.x = v.x * sc[c4]     + shf[c4];
            v.y = v.y * sc[c4 + 1] + shf[c4 + 1];
            v.z = v.z * sc[c4 + 2] + shf[c4 + 2];
            v.w = v.w * sc[c4 + 3] + shf[c4 + 3];
            v.x = (v.x > 0.f) ? v.x : ACT_SLOPE * v.x;
            v.y = (v.y > 0.f) ? v.y : ACT_SLOPE * v.y;
            v.z = (v.z > 0.f) ? v.z : ACT_SLOPE * v.z;
            v.w = (v.w > 0.f) ? v.w : ACT_SLOPE * v.w;
        }
        *(float4*)&xs[lr][c4] = v;
    }
    __syncthreads();

    int ty = tid >> 4, tx = tid & 15;
    int r0 = ty * 4, c0 = tx * 4;
    float acc[4][4];
#pragma unroll
    for (int i = 0; i < 4; i++)
#pragma unroll
        for (int j = 0; j < 4; j++) acc[i][j] = 0.f;

#pragma unroll 16
    for (int k = 0; k < FD; k++) {
        float4 wv = *(const float4*)&Ws[k * FD + c0];
        float x0 = xs[r0][k], x1 = xs[r0 + 1][k], x2 = xs[r0 + 2][k], x3 = xs[r0 + 3][k];
        acc[0][0] += x0 * wv.x; acc[0][1] += x0 * wv.y; acc[0][2] += x0 * wv.z; acc[0][3] += x0 * wv.w;
        acc[1][0] += x1 * wv.x; acc[1][1] += x1 * wv.y; acc[1][2] += x1 * wv.z; acc[1][3] += x1 * wv.w;
        acc[2][0] += x2 * wv.x; acc[2][1] += x2 * wv.y; acc[2][2] += x2 * wv.z; acc[2][3] += x2 * wv.w;
        acc[3][0] += x3 * wv.x; acc[3][1] += x3 * wv.y; acc[3][2] += x3 * wv.z; acc[3][3] += x3 * wv.w;
    }

    float lmS = 0.f, lmD = 0.f;
#pragma unroll
    for (int i = 0; i < 4; i++) {
        int row = row0 + r0 + i;
        if (row < n) {
            __half2 h01 = __floats2half2_rn(acc[i][0], acc[i][1]);
            __half2 h23 = __floats2half2_rn(acc[i][2], acc[i][3]);
            uint2 pk;
            pk.x = *(unsigned*)&h01;
            pk.y = *(unsigned*)&h23;
            ((uint2*)H)[(size_t)row * 16 + tx] = pk;
        }
        float ps = acc[i][0] * as[c0] + acc[i][1] * as[c0 + 1] + acc[i][2] * as[c0 + 2] + acc[i][3] * as[c0 + 3];
        float pd = acc[i][0] * ad[c0] + acc[i][1] * ad[c0 + 1] + acc[i][2] * ad[c0 + 2] + acc[i][3] * ad[c0 + 3];
#pragma unroll
        for (int o = 8; o; o >>= 1) {
            ps += __shfl_down_sync(0xffffffffu, ps, o, 16);
            pd += __shfl_down_sync(0xffffffffu, pd, o, 16);
        }
        if (tx == 0 && row < n) {
            ssrc[row] = ps;
            sdst[row] = pd;
            lmS = fmaxf(lmS, ps);
            lmD = fmaxf(lmD, pd);
        }
    }
#pragma unroll
    for (int o = 16; o; o >>= 1) {
        lmS = fmaxf(lmS, __shfl_xor_sync(0xffffffffu, lmS, o));
        lmD = fmaxf(lmD, __shfl_xor_sync(0xffffffffu, lmD, o));
    }
    int wid = tid >> 5;
    if ((tid & 31) == 0) { wmaxS[wid] = lmS; wmaxD[wid] = lmD; }
    __syncthreads();
    if (tid == 0) {
        float mS = 0.f, mD = 0.f;
#pragma unroll
        for (int w = 0; w < 8; w++) { mS = fmaxf(mS, wmaxS[w]); mD = fmaxf(mD, wmaxD[w]); }
        atomicMax(&g_maxbits[2 * li],     __float_as_int(mS));
        atomicMax(&g_maxbits[2 * li + 1], __float_as_int(mD));
    }
}

// ---------------- Aggregation: warp per dst node, smem (s,w) staging (R8-proven config) ----------------
#define CHUNK 128
#define AGG_BS 256
__global__ void __launch_bounds__(AGG_BS)
agg_kernel(const __half* __restrict__ H,
           const float* __restrict__ ssrc, const float* __restrict__ sdst,
           const float* __restrict__ bias,
           const float* __restrict__ x0,
           float* __restrict__ out, int n, int residual, int li) {
    __shared__ int2 swbuf[AGG_BS / 32][CHUNK];
    int wwarp = threadIdx.x >> 5;
    int warp = (blockIdx.x * blockDim.x + threadIdx.x) >> 5;
    int lane = threadIdx.x & 31;
    if (warp >= n) return;
    float M = __int_as_float(g_maxbits[2 * li]) + __int_as_float(g_maxbits[2 * li + 1]);
    int start = g_rowstart[warp];
    int end   = start + g_deg[warp];
    float sd = sdst[warp];
    int q = lane >> 3, sub = lane & 7;

    float z = 0.0f;
    float acc[8];
#pragma unroll
    for (int i = 0; i < 8; i++) acc[i] = 0.f;
    const uint4* H8 = (const uint4*)H;

    for (int cbase = start; cbase < end; cbase += CHUNK) {
        int cnt = min(CHUNK, end - cbase);
        // ---- phase W: compute (s, w) coalesced, stage to smem ----
        for (int t = cbase + lane; t < cbase + cnt; t += 32) {
            int s = g_csrsrc[t];
            float lg = ssrc[s] + sd;
            lg = (lg > 0.0f) ? lg : ATT_SLOPE * lg;
            float w = __expf(lg - M);
            z += w;
            swbuf[wwarp][t - cbase] = make_int2(s, __float_as_int(w));
        }
        __syncwarp();
        // ---- phase G: quarter-warp per edge, broadcast LDS, streaming LDG.128 ----
#pragma unroll 2
        for (int j = 0; j < cnt; j += 4) {
            int idx = j + q;
            int2 sw = (idx < cnt) ? swbuf[wwarp][idx] : make_int2(0, 0);
            float ej = __int_as_float(sw.y);          // 0.0f when idx >= cnt
            uint4 hv = __ldg(&H8[(size_t)sw.x * 8 + sub]);
            float2 f0 = __half22float2(*(__half2*)&hv.x);
            float2 f1 = __half22float2(*(__half2*)&hv.y);
            float2 f2 = __half22float2(*(__half2*)&hv.z);
            float2 f3 = __half22float2(*(__half2*)&hv.w);
            acc[0] += ej * f0.x; acc[1] += ej * f0.y;
            acc[2] += ej * f1.x; acc[3] += ej * f1.y;
            acc[4] += ej * f2.x; acc[5] += ej * f2.y;
            acc[6] += ej * f3.x; acc[7] += ej * f3.y;
        }
        __syncwarp();
    }
#pragma unroll
    for (int i = 0; i < 8; i++) {
        acc[i] += __shfl_xor_sync(0xffffffffu, acc[i], 8);
        acc[i] += __shfl_xor_sync(0xffffffffu, acc[i], 16);
    }
#pragma unroll
    for (int o = 16; o; o >>= 1) z += __shfl_xor_sync(0xffffffffu, z, o);

    if (q == 0) {
        float inv = 1.0f / z;
        float4 b0 = ((const float4*)bias)[sub * 2];
        float4 b1 = ((const float4*)bias)[sub * 2 + 1];
        float4 r0, r1;
        r0.x = acc[0] * inv + b0.x;
        r0.y = acc[1] * inv + b0.y;
        r0.z = acc[2] * inv + b0.z;
        r0.w = acc[3] * inv + b0.w;
        r1.x = acc[4] * inv + b1.x;
        r1.y = acc[5] * inv + b1.y;
        r1.z = acc[6] * inv + b1.z;
        r1.w = acc[7] * inv + b1.w;
        if (residual) {
            float4 xv0 = ((const float4*)x0)[(size_t)warp * 16 + sub * 2];
            float4 xv1 = ((const float4*)x0)[(size_t)warp * 16 + sub * 2 + 1];
            r0.x = 0.5f * (xv0.x + r0.x); r0.y = 0.5f * (xv0.y + r0.y);
            r0.z = 0.5f * (xv0.z + r0.z); r0.w = 0.5f * (xv0.w + r0.w);
            r1.x = 0.5f * (xv1.x + r1.x); r1.y = 0.5f * (xv1.y + r1.y);
            r1.z = 0.5f * (xv1.z + r1.z); r1.w = 0.5f * (xv1.w + r1.w);
        }
        ((float4*)out)[(size_t)warp * 16 + sub * 2]     = r0;
        ((float4*)out)[(size_t)warp * 16 + sub * 2 + 1] = r1;
    }
}

// ---------------- BN statistics ----------------
__global__ void bnstats_kernel(const float* __restrict__ A, int n) {
    __shared__ float s1[256], s2[256];
    int tid = threadIdx.x;
    int c = tid & 63;
    int q = tid >> 6;
    float sum = 0.f, sq = 0.f;
    int row0 = blockIdx.x * 64;
    for (int rr = q; rr < 64; rr += 4) {
        int row = row0 + rr;
        if (row < n) {
            float v = A[(size_t)row * FD + c];
            sum += v;
            sq  += v * v;
        }
    }
    s1[tid] = sum; s2[tid] = sq;
    __syncthreads();
    if (q == 0) {
        sum = s1[c] + s1[64 + c] + s1[128 + c] + s1[192 + c];
        sq  = s2[c] + s2[64 + c] + s2[128 + c] + s2[192 + c];
        atomicAdd(&g_bnacc[c], sum);
        atomicAdd(&g_bnacc[FD + c], sq);
    }
}

// ---------------- launch ----------------
extern "C" void kernel_launch(void* const* d_in, const int* in_sizes, int n_in,
                              void* d_out, int out_size) {
    const float* x        = (const float*)d_in[0];
    const float* W1       = (const float*)d_in[1];
    const float* att_src1 = (const float*)d_in[2];
    const float* att_dst1 = (const float*)d_in[3];
    const float* bias1    = (const float*)d_in[4];
    const float* bn_gamma = (const float*)d_in[5];
    const float* bn_beta  = (const float*)d_in[6];
    const float* W2       = (const float*)d_in[7];
    const float* att_src2 = (const float*)d_in[8];
    const float* att_dst2 = (const float*)d_in[9];
    const float* bias2    = (const float*)d_in[10];
    const int*   ei       = (const int*)d_in[11];

    int n = in_sizes[0] / FD;
    int e = in_sizes[11] / 2;

    float* out = (float*)d_out;

    __half* d_h   = nullptr;
    float* d_agg  = nullptr;
    float* d_ssrc = nullptr;
    float* d_sdst = nullptr;
    cudaGetSymbolAddress((void**)&d_h, g_h);
    cudaGetSymbolAddress((void**)&d_agg, g_agg);
    cudaGetSymbolAddress((void**)&d_ssrc, g_ssrc);
    cudaGetSymbolAddress((void**)&d_sdst, g_sdst);

    static cudaStream_t s2 = nullptr;
    static cudaEvent_t ev_fork = nullptr, ev_join = nullptr;
    if (!s2) {
        cudaStreamCreateWithFlags(&s2, cudaStreamNonBlocking);
        cudaEventCreateWithFlags(&ev_fork, cudaEventDisableTiming);
        cudaEventCreateWithFlags(&ev_join, cudaEventDisableTiming);
    }

    int nb = (n + SCAN_BS - 1) / SCAN_BS;
    int gemm_grid = (n + 63) / 64;
    int agg_grid  = (n + (AGG_BS / 32) - 1) / (AGG_BS / 32);
    int e4 = (e + 3) / 4;

    // prologue
    zero_kernel<<<(n + 255) / 256, 256>>>(n);

    // fork: GEMM1 concurrent with CSR build
    cudaEventRecord(ev_fork, 0);
    cudaStreamWaitEvent(s2, ev_fork, 0);
    gemm_kernel<<<gemm_grid, 256, 0, s2>>>(x, W1, att_src1, att_dst1,
                                           d_h, d_ssrc, d_sdst, n, 0, nullptr, nullptr, 0);
    cudaEventRecord(ev_join, s2);

    // CSR build on main stream
    count_kernel<<<(e4 + 255) / 256, 256>>>(ei, e);
    scanA_kernel<<<nb, SCAN_BS>>>(n);
    fill_kernel<<<(e4 + 255) / 256, 256>>>(ei, e);

    // join, then layer-1 aggregation
    cudaStreamWaitEvent(0, ev_join, 0);
    agg_kernel<<<agg_grid, AGG_BS>>>(d_h, d_ssrc, d_sdst, bias1, nullptr, d_agg, n, 0, 0);

    // BN stats
    bnstats_kernel<<<(n + 63) / 64, 256>>>(d_agg, n);

    // Layer 2
    gemm_kernel<<<gemm_grid, 256>>>(d_agg, W2, att_src2, att_dst2,
                                    d_h, d_ssrc, d_sdst, n, 1, bn_gamma, bn_beta, 1);
    agg_kernel<<<agg_grid, AGG_BS>>>(d_h, d_ssrc, d_sdst, bias2, x, out, n, 1, 1);
}